// round 3
// baseline (speedup 1.0000x reference)
#include <cuda_runtime.h>
#include <math.h>

#define NN 100000
#define EE 800000
#define ET (EE + NN)
#define GG 128

// ---------------- scratch (static device memory) ----------------
__device__ float d_x384[(size_t)NN * 384];
__device__ float d_h[(size_t)NN * 256];     // current layer h (reused both layers)
__device__ float d_pre[(size_t)NN * 128];   // aggregated pre-activation (reused)
__device__ float d_out1[(size_t)NN * 128];
__device__ float d_out2[(size_t)NN * 128];
__device__ float d_als[NN * 2], d_ald[NN * 2];   // attention logits (reused)
__device__ unsigned d_m[NN * 2];            // per-(dst,head) max (encoded)
__device__ float d_s[NN * 2];               // per-(dst,head) sum-exp
__device__ float d_gh[(size_t)NN * 128];
__device__ float d_lg[NN];
__device__ unsigned d_gm[GG];
__device__ float d_gs[GG];
__device__ float d_pooled[GG * 128];
__device__ int d_i64;

// ---------------- helpers ----------------
__device__ __forceinline__ float sig_(float x) { return 1.f / (1.f + expf(-x)); }
__device__ __forceinline__ float lrelu_(float x) { return x > 0.f ? x : 0.2f * x; }
// order-preserving float<->uint encoding for atomicMax
__device__ __forceinline__ unsigned enc(float f) {
    unsigned u = __float_as_uint(f);
    return (u & 0x80000000u) ? ~u : (u | 0x80000000u);
}
__device__ __forceinline__ float dec(unsigned u) {
    return __uint_as_float((u & 0x80000000u) ? (u & 0x7fffffffu) : ~u);
}
// dtype-robust int read (int64 low word if detected)
__device__ __forceinline__ int gi(const int* __restrict__ p, int i, int m64) {
    return p[m64 ? (i << 1) : i];
}

__global__ void k_detect(const int* __restrict__ ei) {
    if (threadIdx.x == 0)
        d_i64 = ((ei[1] | ei[3] | ei[5] | ei[7] | ei[9]) == 0) ? 1 : 0;
}

// ---------------- x_ = concat(emb_i[x[:,i]]) : [N,384] ----------------
__global__ void k_x384(const int* __restrict__ x,
                       const float* __restrict__ e0, const float* __restrict__ e1,
                       const float* __restrict__ e2, const float* __restrict__ e3,
                       const float* __restrict__ e4, const float* __restrict__ e5) {
    long long t = (long long)blockIdx.x * blockDim.x + threadIdx.x;
    if (t >= (long long)NN * 384) return;
    int n = (int)(t / 384), f = (int)(t % 384);
    int i = f >> 6, c = f & 63;
    int v = gi(x, n * 6 + i, d_i64);
    const float* emb = (i == 0) ? e0 : (i == 1) ? e1 : (i == 2) ? e2 : (i == 3) ? e3 : (i == 4) ? e4 : e5;
    d_x384[t] = emb[v * 64 + c];
}

// ---------------- h = A @ W : one block per row, thread per column ----------------
__global__ void k_gemm1(const float* __restrict__ W1) {   // d_x384[N,384] @ W1[384,256] -> d_h
    int n = blockIdx.x, j = threadIdx.x;                  // 256 threads
    const float* a = d_x384 + (size_t)n * 384;
    float a0 = 0.f, a1 = 0.f;
    for (int f = 0; f < 384; f += 2) {
        a0 = fmaf(a[f],     W1[(size_t)f * 256 + j],       a0);
        a1 = fmaf(a[f + 1], W1[(size_t)(f + 1) * 256 + j], a1);
    }
    d_h[(size_t)n * 256 + j] = a0 + a1;
}

__global__ void k_gemm2(const float* __restrict__ W2) {   // d_out1[N,128] @ W2[128,256] -> d_h
    int n = blockIdx.x, j = threadIdx.x;                  // 256 threads
    const float* a = d_out1 + (size_t)n * 128;
    float a0 = 0.f, a1 = 0.f;
    for (int f = 0; f < 128; f += 2) {
        a0 = fmaf(a[f],     W2[(size_t)f * 256 + j],       a0);
        a1 = fmaf(a[f + 1], W2[(size_t)(f + 1) * 256 + j], a1);
    }
    d_h[(size_t)n * 256 + j] = a0 + a1;
}

// ---------------- attention logits: als/ald per (node, head) ----------------
__global__ void k_al(const float* __restrict__ as_, const float* __restrict__ ad_) {
    int t = blockIdx.x * blockDim.x + threadIdx.x;
    if (t >= NN * 2) return;
    int n = t >> 1, hh = t & 1;
    const float* hrow = d_h + (size_t)n * 256 + hh * 128;
    float s = 0.f, d = 0.f;
    for (int c = 0; c < 128; c++) {
        s = fmaf(hrow[c], as_[hh * 128 + c], s);
        d = fmaf(hrow[c], ad_[hh * 128 + c], d);
    }
    d_als[t] = s;
    d_ald[t] = d;
}

// ---------------- zero/init kernels ----------------
__global__ void k_zpre() {
    long long t = (long long)blockIdx.x * blockDim.x + threadIdx.x;
    if (t < (long long)NN * 128) d_pre[t] = 0.f;
}
__global__ void k_zms() {
    int t = blockIdx.x * blockDim.x + threadIdx.x;
    if (t < NN * 2) { d_m[t] = enc(-3.0e38f); d_s[t] = 0.f; }
}
__global__ void k_zg() {
    int t = blockIdx.x * blockDim.x + threadIdx.x;
    if (t < GG * 128) d_pooled[t] = 0.f;
    if (t < GG) { d_gm[t] = enc(-3.0e38f); d_gs[t] = 0.f; }
}

// ---------------- edge passes: max, sum-exp, aggregate ----------------
__global__ void k_emax(const int* __restrict__ ei) {
    int t = blockIdx.x * blockDim.x + threadIdx.x;
    if (t >= ET) return;
    int m64 = d_i64;
    int s, d;
    if (t < EE) { s = gi(ei, t, m64); d = gi(ei, EE + t, m64); }
    else { s = d = t - EE; }
#pragma unroll
    for (int hh = 0; hh < 2; hh++) {
        float e = lrelu_(d_als[s * 2 + hh] + d_ald[d * 2 + hh]);
        atomicMax(&d_m[d * 2 + hh], enc(e));
    }
}

__global__ void k_esum(const int* __restrict__ ei) {
    int t = blockIdx.x * blockDim.x + threadIdx.x;
    if (t >= ET) return;
    int m64 = d_i64;
    int s, d;
    if (t < EE) { s = gi(ei, t, m64); d = gi(ei, EE + t, m64); }
    else { s = d = t - EE; }
#pragma unroll
    for (int hh = 0; hh < 2; hh++) {
        float e = lrelu_(d_als[s * 2 + hh] + d_ald[d * 2 + hh]);
        atomicAdd(&d_s[d * 2 + hh], expf(e - dec(d_m[d * 2 + hh])));
    }
}

// warp per edge; lane covers 4 channels (stride 32)
__global__ void k_eagg(const int* __restrict__ ei) {
    int w = blockIdx.x * (blockDim.x >> 5) + (threadIdx.x >> 5);
    int lane = threadIdx.x & 31;
    if (w >= ET) return;
    int m64 = d_i64;
    int s, d;
    if (w < EE) { s = gi(ei, w, m64); d = gi(ei, EE + w, m64); }
    else { s = d = w - EE; }
    float e0 = lrelu_(d_als[s * 2 + 0] + d_ald[d * 2 + 0]);
    float e1 = lrelu_(d_als[s * 2 + 1] + d_ald[d * 2 + 1]);
    float w0 = expf(e0 - dec(d_m[d * 2 + 0])) / (d_s[d * 2 + 0] + 1e-16f);
    float w1 = expf(e1 - dec(d_m[d * 2 + 1])) / (d_s[d * 2 + 1] + 1e-16f);
    const float* hs = d_h + (size_t)s * 256;
    float* pd = d_pre + (size_t)d * 128;
#pragma unroll
    for (int q = 0; q < 4; q++) {
        int c = lane + 32 * q;
        atomicAdd(&pd[c], w0 * hs[c] + w1 * hs[128 + c]);
    }
}

// ---------------- activation: out = sigmoid(0.5*pre + b) ----------------
__global__ void k_act(const float* __restrict__ bias, int layer) {
    long long t = (long long)blockIdx.x * blockDim.x + threadIdx.x;
    if (t >= (long long)NN * 128) return;
    float v = sig_(0.5f * d_pre[t] + bias[t & 127]);
    if (layer == 1) d_out1[t] = v; else d_out2[t] = v;
}

// ---------------- gate MLP ----------------
__global__ void k_ghk(const float* __restrict__ gw1, const float* __restrict__ gb1,
                      const float* __restrict__ bng, const float* __restrict__ bnb,
                      const float* __restrict__ bnm, const float* __restrict__ bnv) {
    int n = blockIdx.x, j = threadIdx.x;   // 128 threads
    const float* a = d_out2 + (size_t)n * 128;
    float acc = 0.f;
    for (int f = 0; f < 128; f++) acc = fmaf(a[f], gw1[(size_t)f * 128 + j], acc);
    float v = (acc + gb1[j] - bnm[j]) / sqrtf(bnv[j] + 1e-5f) * bng[j] + bnb[j];
    d_gh[(size_t)n * 128 + j] = v > 0.f ? v : 0.f;
}

__global__ void k_lg(const float* __restrict__ gw2, const float* __restrict__ gb2) {
    int n = blockIdx.x * blockDim.x + threadIdx.x;
    if (n >= NN) return;
    const float* g = d_gh + (size_t)n * 128;
    float acc = 0.f;
    for (int j = 0; j < 128; j++) acc = fmaf(g[j], gw2[j], acc);
    d_lg[n] = acc + gb2[0];
}

// ---------------- gate softmax over graphs + pooling ----------------
__global__ void k_gmax(const int* __restrict__ batch) {
    int n = blockIdx.x * blockDim.x + threadIdx.x;
    if (n >= NN) return;
    atomicMax(&d_gm[gi(batch, n, d_i64)], enc(d_lg[n]));
}
__global__ void k_gsum(const int* __restrict__ batch) {
    int n = blockIdx.x * blockDim.x + threadIdx.x;
    if (n >= NN) return;
    int b = gi(batch, n, d_i64);
    atomicAdd(&d_gs[b], expf(d_lg[n] - dec(d_gm[b])));
}
__global__ void k_gpool(const int* __restrict__ batch) {
    long long t = (long long)blockIdx.x * blockDim.x + threadIdx.x;
    if (t >= (long long)NN * 128) return;
    int n = (int)(t >> 7), j = (int)(t & 127);
    int b = gi(batch, n, d_i64);
    float gate = expf(d_lg[n] - dec(d_gm[b])) / (d_gs[b] + 1e-16f);
    atomicAdd(&d_pooled[b * 128 + j], gate * d_out2[(size_t)n * 128 + j]);
}

__global__ void k_fin(const float* __restrict__ glw, const float* __restrict__ glb,
                      float* __restrict__ out) {
    int g = threadIdx.x;
    if (g >= GG) return;
    float acc = 0.f;
    for (int j = 0; j < 128; j++) acc = fmaf(d_pooled[g * 128 + j], glw[j], acc);
    out[g] = sig_(acc + glb[0]);
}

// ---------------- launch ----------------
extern "C" void kernel_launch(void* const* d_in, const int* in_sizes, int n_in,
                              void* d_out, int out_size) {
    const int* x     = (const int*)d_in[0];
    const int* ei    = (const int*)d_in[1];
    const int* batch = (const int*)d_in[3];
    const float* emb0 = (const float*)d_in[4];
    const float* emb1 = (const float*)d_in[5];
    const float* emb2 = (const float*)d_in[6];
    const float* emb3 = (const float*)d_in[7];
    const float* emb4 = (const float*)d_in[8];
    const float* emb5 = (const float*)d_in[9];
    const float* W1  = (const float*)d_in[10];
    const float* as1 = (const float*)d_in[11];
    const float* ad1 = (const float*)d_in[12];
    const float* b1  = (const float*)d_in[13];
    const float* W2  = (const float*)d_in[14];
    const float* as2 = (const float*)d_in[15];
    const float* ad2 = (const float*)d_in[16];
    const float* b2  = (const float*)d_in[17];
    const float* gw1 = (const float*)d_in[18];
    const float* gb1 = (const float*)d_in[19];
    const float* bng = (const float*)d_in[20];
    const float* bnb = (const float*)d_in[21];
    const float* bnm = (const float*)d_in[22];
    const float* bnv = (const float*)d_in[23];
    const float* gw2 = (const float*)d_in[24];
    const float* gb2 = (const float*)d_in[25];
    const float* glw = (const float*)d_in[26];
    const float* glb = (const float*)d_in[27];
    float* out = (float*)d_out;

    const long long NF = (long long)NN * 128;
    const int gNF = (int)((NF + 255) / 256);

    k_detect<<<1, 32>>>(ei);

    // layer 1
    k_x384<<<(int)(((long long)NN * 384 + 255) / 256), 256>>>(x, emb0, emb1, emb2, emb3, emb4, emb5);
    k_gemm1<<<NN, 256>>>(W1);
    k_al<<<(NN * 2 + 255) / 256, 256>>>(as1, ad1);
    k_zpre<<<gNF, 256>>>();
    k_zms<<<(NN * 2 + 255) / 256, 256>>>();
    k_emax<<<(ET + 255) / 256, 256>>>(ei);
    k_esum<<<(ET + 255) / 256, 256>>>(ei);
    k_eagg<<<ET / 8, 256>>>(ei);
    k_act<<<gNF, 256>>>(b1, 1);

    // layer 2
    k_gemm2<<<NN, 256>>>(W2);
    k_al<<<(NN * 2 + 255) / 256, 256>>>(as2, ad2);
    k_zpre<<<gNF, 256>>>();
    k_zms<<<(NN * 2 + 255) / 256, 256>>>();
    k_emax<<<(ET + 255) / 256, 256>>>(ei);
    k_esum<<<(ET + 255) / 256, 256>>>(ei);
    k_eagg<<<ET / 8, 256>>>(ei);
    k_act<<<gNF, 256>>>(b2, 2);

    // gate + pooling
    k_ghk<<<NN, 128>>>(gw1, gb1, bng, bnb, bnm, bnv);
    k_lg<<<(NN + 255) / 256, 256>>>(gw2, gb2);
    k_zg<<<(GG * 128 + 255) / 256, 256>>>();
    k_gmax<<<(NN + 255) / 256, 256>>>(batch);
    k_gsum<<<(NN + 255) / 256, 256>>>(batch);
    k_gpool<<<gNF, 256>>>(batch);
    k_fin<<<1, 128>>>(glw, glb, out);

    (void)in_sizes; (void)n_in; (void)out_size;
}

// round 4
// speedup vs baseline: 2.3048x; 2.3048x over previous
#include <cuda_runtime.h>
#include <math.h>

#define NN 100000
#define EE 800000
#define ET (EE + NN)
#define GG 128
#define FULL 0xffffffffu

typedef unsigned long long ull;

// ---------------- scratch (static device memory) ----------------
__device__ float d_x384[(size_t)NN * 384];
__device__ float d_h[(size_t)NN * 256];
__device__ float d_pre[(size_t)NN * 128];
__device__ float d_out1[(size_t)NN * 128];
__device__ float d_out2[(size_t)NN * 128];
__device__ float d_als[NN * 2], d_ald[NN * 2];
__device__ float d_s[NN * 2];
__device__ float d_ew[(size_t)ET * 2];
__device__ float d_gh[(size_t)NN * 128];
__device__ float d_lg[NN], d_eg[NN];
__device__ float d_gs[GG];
__device__ float d_pooled[GG * 128];
__device__ int d_i64;

// ---------------- helpers ----------------
__device__ __forceinline__ float sig_(float x) { return 1.f / (1.f + __expf(-x)); }
__device__ __forceinline__ float lrelu_(float x) { return x > 0.f ? x : 0.2f * x; }
__device__ __forceinline__ float warpSum(float v) {
#pragma unroll
    for (int o = 16; o; o >>= 1) v += __shfl_xor_sync(FULL, v, o);
    return v;
}
__device__ __forceinline__ float dot4(float4 a, float4 b) {
    return a.x * b.x + a.y * b.y + a.z * b.z + a.w * b.w;
}
__device__ __forceinline__ int gi(const int* __restrict__ p, int i, int m64) {
    return p[m64 ? (i << 1) : i];
}
__device__ __forceinline__ ull pack2(float x, float y) {
    ull r;
    asm("mov.b64 %0, {%1, %2};" : "=l"(r) : "f"(x), "f"(y));
    return r;
}
__device__ __forceinline__ void ffma2(ull& d, ull a, ull b) {
    asm("fma.rn.f32x2 %0, %1, %2, %0;" : "+l"(d) : "l"(a), "l"(b));
}

__global__ void k_detect(const int* __restrict__ ei) {
    if (threadIdx.x == 0)
        d_i64 = ((ei[1] | ei[3] | ei[5] | ei[7] | ei[9]) == 0) ? 1 : 0;
}

// ---------------- x_ = concat(emb_i[x[:,i]]) : [N,384], float4 ----------------
__global__ void k_x384(const int* __restrict__ x,
                       const float* __restrict__ e0, const float* __restrict__ e1,
                       const float* __restrict__ e2, const float* __restrict__ e3,
                       const float* __restrict__ e4, const float* __restrict__ e5) {
    long long t = (long long)blockIdx.x * blockDim.x + threadIdx.x;
    if (t >= (long long)NN * 96) return;
    int n = (int)(t / 96), f4 = (int)(t % 96);
    int i = f4 >> 4, c4 = f4 & 15;
    int v = gi(x, n * 6 + i, d_i64);
    const float* emb = (i == 0) ? e0 : (i == 1) ? e1 : (i == 2) ? e2 : (i == 3) ? e3 : (i == 4) ? e4 : e5;
    ((float4*)d_x384)[t] = ((const float4*)emb)[v * 16 + c4];
}

// ---------------- tiled SGEMM: C[M,NC] = A[M,KT] @ B[KT,NC], f32x2 FMA ----------------
// 512 threads, BM=64 (4 rows/thread), BK=128, full NC staged in smem.
template <int NC, int KT>
__global__ void k_sgemm(const float* __restrict__ A, const float* __restrict__ B,
                        float* __restrict__ C, int M) {
    constexpr int BM = 64, BK = 128, NR = NC / 32;
    extern __shared__ float sm[];
    float* Bs = sm;            // [BK][NC]
    float* As = sm + BK * NC;  // [BM][BK]
    int tid = threadIdx.x;
    int row0 = blockIdx.x * BM;
    int tn = tid & 31, tm = tid >> 5;   // tm in [0,16)

    ull acc2[4][NR / 2];
#pragma unroll
    for (int r = 0; r < 4; r++)
#pragma unroll
        for (int q = 0; q < NR / 2; q++) acc2[r][q] = 0ull;

    for (int k0 = 0; k0 < KT; k0 += BK) {
        {   // B chunk: rows k0..k0+BK contiguous
            const float4* Bg = (const float4*)(B + (size_t)k0 * NC);
            float4* Bs4 = (float4*)Bs;
#pragma unroll
            for (int u = 0; u < (BK * NC / 4) / 512; u++)
                Bs4[tid + 512 * u] = __ldg(Bg + tid + 512 * u);
        }
        {   // A chunk: [BM][BK]
            float4* As4 = (float4*)As;
#pragma unroll
            for (int u = 0; u < (BM * BK / 4) / 512; u++) {
                int f = tid + 512 * u;
                int r = f >> 5, c4 = f & 31;
                int gr = row0 + r;
                float4 v = make_float4(0.f, 0.f, 0.f, 0.f);
                if (gr < M) v = __ldg((const float4*)(A + (size_t)gr * KT) + (k0 >> 2) + c4);
                As4[f] = v;
            }
        }
        __syncthreads();
        const float* Ab = As + (tm * 4) * BK;
#pragma unroll 4
        for (int k = 0; k < BK; k++) {
            ull a2[4];
#pragma unroll
            for (int r = 0; r < 4; r++) { float av = Ab[r * BK + k]; a2[r] = pack2(av, av); }
            ull b2[NR / 2];
            const float4* bp = (const float4*)(Bs + k * NC + tn * NR);
#pragma unroll
            for (int q = 0; q < NR / 4; q++) {
                float4 tv = bp[q];
                b2[2 * q]     = pack2(tv.x, tv.y);
                b2[2 * q + 1] = pack2(tv.z, tv.w);
            }
#pragma unroll
            for (int r = 0; r < 4; r++)
#pragma unroll
                for (int q = 0; q < NR / 2; q++) ffma2(acc2[r][q], a2[r], b2[q]);
        }
        __syncthreads();
    }
#pragma unroll
    for (int r = 0; r < 4; r++) {
        int gr = row0 + tm * 4 + r;
        if (gr < M) {
            ull* cp = (ull*)(C + (size_t)gr * NC + tn * NR);
#pragma unroll
            for (int q = 0; q < NR / 2; q++) cp[q] = acc2[r][q];
        }
    }
}

// ---------------- attention logits: warp per node, float4 ----------------
__global__ void k_al(const float* __restrict__ as_, const float* __restrict__ ad_) {
    int n = blockIdx.x * 8 + (threadIdx.x >> 5);
    int lane = threadIdx.x & 31;
    if (n >= NN) return;
    const float4* hp = (const float4*)(d_h + (size_t)n * 256);
    float4 h0 = __ldg(hp + lane), h1 = __ldg(hp + lane + 32);
    float4 s0 = __ldg((const float4*)as_ + lane), s1 = __ldg((const float4*)as_ + lane + 32);
    float4 t0 = __ldg((const float4*)ad_ + lane), t1 = __ldg((const float4*)ad_ + lane + 32);
    float ps0 = warpSum(dot4(h0, s0));
    float ps1 = warpSum(dot4(h1, s1));
    float pd0 = warpSum(dot4(h0, t0));
    float pd1 = warpSum(dot4(h1, t1));
    if (lane == 0) {
        d_als[n * 2] = ps0; d_als[n * 2 + 1] = ps1;
        d_ald[n * 2] = pd0; d_ald[n * 2 + 1] = pd1;
    }
}

// ---------------- zero pass (d_pre + d_s) ----------------
__global__ void k_zero() {
    long long t = (long long)blockIdx.x * blockDim.x + threadIdx.x;
    if (t < (long long)NN * 128) d_pre[t] = 0.f;
    if (t < NN * 2) d_s[t] = 0.f;
}
__global__ void k_zg() {
    int t = blockIdx.x * blockDim.x + threadIdx.x;
    if (t < GG * 128) d_pooled[t] = 0.f;
    if (t < GG) d_gs[t] = 0.f;
}

// ---------------- edge pass 1: w = exp(leaky(als[s]+ald[d])); sum per (dst,head) ----------------
__global__ void k_esum(const int* __restrict__ ei) {
    int t = blockIdx.x * blockDim.x + threadIdx.x;
    if (t >= ET) return;
    int m64 = d_i64;
    int s, d;
    if (t < EE) { s = gi(ei, t, m64); d = gi(ei, EE + t, m64); }
    else { s = d = t - EE; }
    float2 asv = ((const float2*)d_als)[s];
    float2 adv = ((const float2*)d_ald)[d];
    float w0 = __expf(lrelu_(asv.x + adv.x));
    float w1 = __expf(lrelu_(asv.y + adv.y));
    ((float2*)d_ew)[t] = make_float2(w0, w1);
    atomicAdd(&d_s[d * 2],     w0);
    atomicAdd(&d_s[d * 2 + 1], w1);
}

// ---------------- edge pass 2: aggregate (warp per edge, float4 loads) ----------------
__global__ void k_eagg(const int* __restrict__ ei) {
    int w = blockIdx.x * (blockDim.x >> 5) + (threadIdx.x >> 5);
    int lane = threadIdx.x & 31;
    if (w >= ET) return;
    int m64 = d_i64;
    int s, d;
    if (w < EE) { s = gi(ei, w, m64); d = gi(ei, EE + w, m64); }
    else { s = d = w - EE; }
    float2 ww = ((const float2*)d_ew)[w];
    float2 sv = ((const float2*)d_s)[d];
    float w0 = ww.x / (sv.x + 1e-16f);
    float w1 = ww.y / (sv.y + 1e-16f);
    const float4* hs = (const float4*)(d_h + (size_t)s * 256);
    float4 v0 = __ldg(hs + lane);
    float4 v1 = __ldg(hs + lane + 32);
    float* pd = d_pre + (size_t)d * 128 + lane * 4;
    atomicAdd(pd + 0, w0 * v0.x + w1 * v1.x);
    atomicAdd(pd + 1, w0 * v0.y + w1 * v1.y);
    atomicAdd(pd + 2, w0 * v0.z + w1 * v1.z);
    atomicAdd(pd + 3, w0 * v0.w + w1 * v1.w);
}

// ---------------- activation: out = sigmoid(0.5*pre + b) ----------------
__global__ void k_act(const float* __restrict__ bias, float* __restrict__ dst) {
    long long t = (long long)blockIdx.x * blockDim.x + threadIdx.x;
    if (t >= (long long)NN * 128) return;
    dst[t] = sig_(0.5f * d_pre[t] + __ldg(&bias[t & 127]));
}

// ---------------- gate: BN + relu elementwise (after sgemm into d_gh) ----------------
__global__ void k_bnrelu(const float* __restrict__ gb1,
                         const float* __restrict__ bng, const float* __restrict__ bnb,
                         const float* __restrict__ bnm, const float* __restrict__ bnv) {
    long long t = (long long)blockIdx.x * blockDim.x + threadIdx.x;
    if (t >= (long long)NN * 128) return;
    int j = (int)(t & 127);
    float v = (d_gh[t] + gb1[j] - bnm[j]) * rsqrtf(bnv[j] + 1e-5f) * bng[j] + bnb[j];
    d_gh[t] = v > 0.f ? v : 0.f;
}

// ---------------- gate logit: warp per node ----------------
__global__ void k_lg(const float* __restrict__ gw2, const float* __restrict__ gb2) {
    int n = blockIdx.x * 8 + (threadIdx.x >> 5);
    int lane = threadIdx.x & 31;
    if (n >= NN) return;
    float4 g = __ldg((const float4*)(d_gh + (size_t)n * 128) + lane);
    float4 w = __ldg((const float4*)gw2 + lane);
    float p = warpSum(dot4(g, w));
    if (lane == 0) d_lg[n] = p + __ldg(gb2);
}

// ---------------- gate softmax (no max; logits provably tiny) + pooling ----------------
__global__ void k_gsum(const int* __restrict__ batch) {
    int n = blockIdx.x * blockDim.x + threadIdx.x;
    if (n >= NN) return;
    float e = __expf(d_lg[n]);
    d_eg[n] = e;
    atomicAdd(&d_gs[gi(batch, n, d_i64)], e);
}
__global__ void k_gpool(const int* __restrict__ batch) {
    long long t = (long long)blockIdx.x * blockDim.x + threadIdx.x;
    if (t >= (long long)NN * 32) return;
    int n = (int)(t >> 5), q = (int)(t & 31);
    int b = gi(batch, n, d_i64);
    float gate = d_eg[n] / (d_gs[b] + 1e-16f);
    float4 v = __ldg((const float4*)(d_out2 + (size_t)n * 128) + q);
    float* pp = d_pooled + b * 128 + q * 4;
    atomicAdd(pp + 0, gate * v.x);
    atomicAdd(pp + 1, gate * v.y);
    atomicAdd(pp + 2, gate * v.z);
    atomicAdd(pp + 3, gate * v.w);
}

__global__ void k_fin(const float* __restrict__ glw, const float* __restrict__ glb,
                      float* __restrict__ out) {
    int g = (blockIdx.x * blockDim.x + threadIdx.x) >> 5;
    int lane = threadIdx.x & 31;
    if (g >= GG) return;
    float4 p = ((const float4*)(d_pooled + g * 128))[lane];
    float4 w = __ldg((const float4*)glw + lane);
    float acc = warpSum(dot4(p, w));
    if (lane == 0) out[g] = sig_(acc + __ldg(glb));
}

// ---------------- launch ----------------
extern "C" void kernel_launch(void* const* d_in, const int* in_sizes, int n_in,
                              void* d_out, int out_size) {
    const int* x     = (const int*)d_in[0];
    const int* ei    = (const int*)d_in[1];
    const int* batch = (const int*)d_in[3];
    const float* emb0 = (const float*)d_in[4];
    const float* emb1 = (const float*)d_in[5];
    const float* emb2 = (const float*)d_in[6];
    const float* emb3 = (const float*)d_in[7];
    const float* emb4 = (const float*)d_in[8];
    const float* emb5 = (const float*)d_in[9];
    const float* W1  = (const float*)d_in[10];
    const float* as1 = (const float*)d_in[11];
    const float* ad1 = (const float*)d_in[12];
    const float* b1  = (const float*)d_in[13];
    const float* W2  = (const float*)d_in[14];
    const float* as2 = (const float*)d_in[15];
    const float* ad2 = (const float*)d_in[16];
    const float* b2  = (const float*)d_in[17];
    const float* gw1 = (const float*)d_in[18];
    const float* gb1 = (const float*)d_in[19];
    const float* bng = (const float*)d_in[20];
    const float* bnb = (const float*)d_in[21];
    const float* bnm = (const float*)d_in[22];
    const float* bnv = (const float*)d_in[23];
    const float* gw2 = (const float*)d_in[24];
    const float* gb2 = (const float*)d_in[25];
    const float* glw = (const float*)d_in[26];
    const float* glb = (const float*)d_in[27];
    float* out = (float*)d_out;

    float* p_h;    cudaGetSymbolAddress((void**)&p_h, d_h);
    float* p_x;    cudaGetSymbolAddress((void**)&p_x, d_x384);
    float* p_o1;   cudaGetSymbolAddress((void**)&p_o1, d_out1);
    float* p_o2;   cudaGetSymbolAddress((void**)&p_o2, d_out2);
    float* p_gh;   cudaGetSymbolAddress((void**)&p_gh, d_gh);

    const int smem256 = (128 * 256 + 64 * 128) * 4;  // 160 KB
    const int smem128 = (128 * 128 + 64 * 128) * 4;  //  96 KB
    cudaFuncSetAttribute((const void*)k_sgemm<256, 384>, cudaFuncAttributeMaxDynamicSharedMemorySize, smem256);
    cudaFuncSetAttribute((const void*)k_sgemm<256, 128>, cudaFuncAttributeMaxDynamicSharedMemorySize, smem256);
    cudaFuncSetAttribute((const void*)k_sgemm<128, 128>, cudaFuncAttributeMaxDynamicSharedMemorySize, smem128);

    const long long NF = (long long)NN * 128;
    const int gNF = (int)((NF + 255) / 256);
    const int gEDGE = (ET + 255) / 256;
    const int gWEDGE = (ET + 7) / 8;      // warp-per-edge, 256-thr blocks
    const int gNODE = NN / 8;             // warp-per-node, 256-thr blocks
    const int gGEMM = (NN + 63) / 64;

    k_detect<<<1, 32>>>(ei);

    // layer 1
    k_x384<<<(int)(((long long)NN * 96 + 255) / 256), 256>>>(x, emb0, emb1, emb2, emb3, emb4, emb5);
    k_sgemm<256, 384><<<gGEMM, 512, smem256>>>(p_x, W1, p_h, NN);
    k_al<<<gNODE, 256>>>(as1, ad1);
    k_zero<<<gNF, 256>>>();
    k_esum<<<gEDGE, 256>>>(ei);
    k_eagg<<<gWEDGE, 256>>>(ei);
    k_act<<<gNF, 256>>>(b1, p_o1);

    // layer 2
    k_sgemm<256, 128><<<gGEMM, 512, smem256>>>(p_o1, W2, p_h, NN);
    k_al<<<gNODE, 256>>>(as2, ad2);
    k_zero<<<gNF, 256>>>();
    k_esum<<<gEDGE, 256>>>(ei);
    k_eagg<<<gWEDGE, 256>>>(ei);
    k_act<<<gNF, 256>>>(b2, p_o2);

    // gate + pooling
    k_sgemm<128, 128><<<gGEMM, 512, smem128>>>(p_o2, gw1, p_gh, NN);
    k_bnrelu<<<gNF, 256>>>(gb1, bng, bnb, bnm, bnv);
    k_lg<<<gNODE, 256>>>(gw2, gb2);
    k_zg<<<(GG * 128 + 255) / 256, 256>>>();
    k_gsum<<<(NN + 255) / 256, 256>>>(batch);
    k_gpool<<<(int)(((long long)NN * 32 + 255) / 256), 256>>>(batch);
    k_fin<<<(GG * 32 + 255) / 256, 256>>>(glw, glb, out);

    (void)in_sizes; (void)n_in; (void)out_size;
}

// round 5
// speedup vs baseline: 2.9574x; 1.2832x over previous
#include <cuda_runtime.h>
#include <math.h>

#define NN 100000
#define EE 800000
#define ET (EE + NN)
#define GG 128
#define NB 98   /* ceil(NN/1024) */
#define FULL 0xffffffffu

typedef unsigned long long ull;

// ---------------- scratch (static device memory) ----------------
__device__ float d_x384[(size_t)NN * 384];
__device__ float d_h[(size_t)NN * 256];
__device__ float d_out1[(size_t)NN * 128];
__device__ float d_out2[(size_t)NN * 128];
__device__ float d_als[NN * 2], d_ald[NN * 2];
__device__ float d_gh[(size_t)NN * 128];
__device__ float d_lg[NN], d_eg[NN];
__device__ float d_gs[GG];
__device__ float d_pooled[GG * 128];
__device__ int d_deg[NN], d_incl[NN], d_ptr[NN + 1], d_pos[NN];
__device__ int d_srcs[ET];
__device__ int d_bsum[128], d_boff[128];
__device__ int d_i64;

// ---------------- helpers ----------------
__device__ __forceinline__ float sig_(float x) { return 1.f / (1.f + __expf(-x)); }
__device__ __forceinline__ float lrelu_(float x) { return x > 0.f ? x : 0.2f * x; }
__device__ __forceinline__ float warpSum(float v) {
#pragma unroll
    for (int o = 16; o; o >>= 1) v += __shfl_xor_sync(FULL, v, o);
    return v;
}
__device__ __forceinline__ float dot4(float4 a, float4 b) {
    return a.x * b.x + a.y * b.y + a.z * b.z + a.w * b.w;
}
__device__ __forceinline__ int gi(const int* __restrict__ p, int i, int m64) {
    return p[m64 ? (i << 1) : i];
}
__device__ __forceinline__ ull pack2(float x, float y) {
    ull r;
    asm("mov.b64 %0, {%1, %2};" : "=l"(r) : "f"(x), "f"(y));
    return r;
}
__device__ __forceinline__ void ffma2(ull& d, ull a, ull b) {
    asm("fma.rn.f32x2 %0, %1, %2, %0;" : "+l"(d) : "l"(a), "l"(b));
}

__global__ void k_detect(const int* __restrict__ ei) {
    if (threadIdx.x == 0)
        d_i64 = ((ei[1] | ei[3] | ei[5] | ei[7] | ei[9]) == 0) ? 1 : 0;
}

// ---------------- CSR build (sort edges by dst; self-loops appended) ----------------
__global__ void k_init() {
    int i = blockIdx.x * blockDim.x + threadIdx.x;
    if (i < NN) d_deg[i] = 1;   // self-loop
}
__global__ void k_hist(const int* __restrict__ ei) {
    int t = blockIdx.x * blockDim.x + threadIdx.x;
    if (t < EE) atomicAdd(&d_deg[gi(ei, EE + t, d_i64)], 1);
}
__global__ void k_scan1() {
    __shared__ int ws[32];
    int i = blockIdx.x * 1024 + threadIdx.x;
    int lane = threadIdx.x & 31, w = threadIdx.x >> 5;
    int x = (i < NN) ? d_deg[i] : 0;
#pragma unroll
    for (int o = 1; o < 32; o <<= 1) { int y = __shfl_up_sync(FULL, x, o); if (lane >= o) x += y; }
    if (lane == 31) ws[w] = x;
    __syncthreads();
    if (w == 0) {
        int t = ws[lane];
#pragma unroll
        for (int o = 1; o < 32; o <<= 1) { int y = __shfl_up_sync(FULL, t, o); if (lane >= o) t += y; }
        ws[lane] = t;
    }
    __syncthreads();
    x += (w > 0) ? ws[w - 1] : 0;
    if (i < NN) d_incl[i] = x;
    if (threadIdx.x == 1023) d_bsum[blockIdx.x] = x;
}
__global__ void k_scan2() {
    if (threadIdx.x == 0) {
        int r = 0;
        for (int b = 0; b < NB; b++) { d_boff[b] = r; r += d_bsum[b]; }
    }
}
__global__ void k_scan3() {
    int i = blockIdx.x * 1024 + threadIdx.x;
    if (i < NN) {
        int e = d_incl[i] - d_deg[i] + d_boff[blockIdx.x];
        d_ptr[i] = e;
        d_pos[i] = e;
    }
    if (i == 0) d_ptr[NN] = ET;
}
__global__ void k_scatter(const int* __restrict__ ei) {
    int t = blockIdx.x * blockDim.x + threadIdx.x;
    if (t >= ET) return;
    int m64 = d_i64;
    int s, d;
    if (t < EE) { s = gi(ei, t, m64); d = gi(ei, EE + t, m64); }
    else { s = d = t - EE; }
    d_srcs[atomicAdd(&d_pos[d], 1)] = s;
}

// ---------------- x_ = concat(emb_i[x[:,i]]) : [N,384], float4 ----------------
__global__ void k_x384(const int* __restrict__ x,
                       const float* __restrict__ e0, const float* __restrict__ e1,
                       const float* __restrict__ e2, const float* __restrict__ e3,
                       const float* __restrict__ e4, const float* __restrict__ e5) {
    long long t = (long long)blockIdx.x * blockDim.x + threadIdx.x;
    if (t >= (long long)NN * 96) return;
    int n = (int)(t / 96), f4 = (int)(t % 96);
    int i = f4 >> 4, c4 = f4 & 15;
    int v = gi(x, n * 6 + i, d_i64);
    const float* emb = (i == 0) ? e0 : (i == 1) ? e1 : (i == 2) ? e2 : (i == 3) ? e3 : (i == 4) ? e4 : e5;
    ((float4*)d_x384)[t] = ((const float4*)emb)[v * 16 + c4];
}

// ---------------- tiled SGEMM: C[M,NC] = A[M,KT] @ B[KT,NC], f32x2 FMA ----------------
template <int NC, int KT>
__global__ void k_sgemm(const float* __restrict__ A, const float* __restrict__ B,
                        float* __restrict__ C, int M) {
    constexpr int BM = 64, BK = 128, NR = NC / 32;
    extern __shared__ float sm[];
    float* Bs = sm;            // [BK][NC]
    float* As = sm + BK * NC;  // [BM][BK]
    int tid = threadIdx.x;
    int row0 = blockIdx.x * BM;
    int tn = tid & 31, tm = tid >> 5;

    ull acc2[4][NR / 2];
#pragma unroll
    for (int r = 0; r < 4; r++)
#pragma unroll
        for (int q = 0; q < NR / 2; q++) acc2[r][q] = 0ull;

    for (int k0 = 0; k0 < KT; k0 += BK) {
        {
            const float4* Bg = (const float4*)(B + (size_t)k0 * NC);
            float4* Bs4 = (float4*)Bs;
#pragma unroll
            for (int u = 0; u < (BK * NC / 4) / 512; u++)
                Bs4[tid + 512 * u] = __ldg(Bg + tid + 512 * u);
        }
        {
            float4* As4 = (float4*)As;
#pragma unroll
            for (int u = 0; u < (BM * BK / 4) / 512; u++) {
                int f = tid + 512 * u;
                int r = f >> 5, c4 = f & 31;
                int gr = row0 + r;
                float4 v = make_float4(0.f, 0.f, 0.f, 0.f);
                if (gr < M) v = __ldg((const float4*)(A + (size_t)gr * KT) + (k0 >> 2) + c4);
                As4[f] = v;
            }
        }
        __syncthreads();
        const float* Ab = As + (tm * 4) * BK;
#pragma unroll 4
        for (int k = 0; k < BK; k++) {
            ull a2[4];
#pragma unroll
            for (int r = 0; r < 4; r++) { float av = Ab[r * BK + k]; a2[r] = pack2(av, av); }
            ull b2[NR / 2];
            const float4* bp = (const float4*)(Bs + k * NC + tn * NR);
#pragma unroll
            for (int q = 0; q < NR / 4; q++) {
                float4 tv = bp[q];
                b2[2 * q]     = pack2(tv.x, tv.y);
                b2[2 * q + 1] = pack2(tv.z, tv.w);
            }
#pragma unroll
            for (int r = 0; r < 4; r++)
#pragma unroll
                for (int q = 0; q < NR / 2; q++) ffma2(acc2[r][q], a2[r], b2[q]);
        }
        __syncthreads();
    }
#pragma unroll
    for (int r = 0; r < 4; r++) {
        int gr = row0 + tm * 4 + r;
        if (gr < M) {
            ull* cp = (ull*)(C + (size_t)gr * NC + tn * NR);
#pragma unroll
            for (int q = 0; q < NR / 2; q++) cp[q] = acc2[r][q];
        }
    }
}

// ---------------- attention logits: warp per node, float4 ----------------
__global__ void k_al(const float* __restrict__ as_, const float* __restrict__ ad_) {
    int n = blockIdx.x * 8 + (threadIdx.x >> 5);
    int lane = threadIdx.x & 31;
    if (n >= NN) return;
    const float4* hp = (const float4*)(d_h + (size_t)n * 256);
    float4 h0 = __ldg(hp + lane), h1 = __ldg(hp + lane + 32);
    float4 s0 = __ldg((const float4*)as_ + lane), s1 = __ldg((const float4*)as_ + lane + 32);
    float4 t0 = __ldg((const float4*)ad_ + lane), t1 = __ldg((const float4*)ad_ + lane + 32);
    float ps0 = warpSum(dot4(h0, s0));
    float ps1 = warpSum(dot4(h1, s1));
    float pd0 = warpSum(dot4(h0, t0));
    float pd1 = warpSum(dot4(h1, t1));
    if (lane == 0) {
        d_als[n * 2] = ps0; d_als[n * 2 + 1] = ps1;
        d_ald[n * 2] = pd0; d_ald[n * 2 + 1] = pd1;
    }
}

// ---------------- fused GAT: single-pass unnormalized gather, warp per dst ----------------
__global__ void k_gat(const float* __restrict__ bias, float* __restrict__ out) {
    int n = blockIdx.x * 8 + (threadIdx.x >> 5);
    int lane = threadIdx.x & 31;
    if (n >= NN) return;
    int p0 = d_ptr[n], p1 = d_ptr[n + 1];
    int deg = p1 - p0;
    float2 adv = ((const float2*)d_ald)[n];

    float4 acc0 = make_float4(0.f, 0.f, 0.f, 0.f);
    float4 acc1 = make_float4(0.f, 0.f, 0.f, 0.f);
    float s0 = 0.f, s1 = 0.f;

    for (int base = 0; base < deg; base += 32) {
        int i = base + lane;
        float w0 = 0.f, w1 = 0.f; int s = 0;
        if (i < deg) {
            s = d_srcs[p0 + i];
            float2 asv = ((const float2*)d_als)[s];
            w0 = __expf(lrelu_(asv.x + adv.x));
            w1 = __expf(lrelu_(asv.y + adv.y));
            s0 += w0; s1 += w1;
        }
        int cnt = min(32, deg - base);
        for (int j = 0; j < cnt; j++) {
            int sj  = __shfl_sync(FULL, s, j);
            float c0 = __shfl_sync(FULL, w0, j);
            float c1 = __shfl_sync(FULL, w1, j);
            const float4* hp = (const float4*)(d_h + (size_t)sj * 256);
            float4 v0 = __ldg(hp + lane);
            float4 v1 = __ldg(hp + lane + 32);
            acc0.x = fmaf(c0, v0.x, acc0.x); acc1.x = fmaf(c1, v1.x, acc1.x);
            acc0.y = fmaf(c0, v0.y, acc0.y); acc1.y = fmaf(c1, v1.y, acc1.y);
            acc0.z = fmaf(c0, v0.z, acc0.z); acc1.z = fmaf(c1, v1.z, acc1.z);
            acc0.w = fmaf(c0, v0.w, acc0.w); acc1.w = fmaf(c1, v1.w, acc1.w);
        }
    }
    s0 = warpSum(s0); s1 = warpSum(s1);
    float i0 = 0.5f / (s0 + 1e-16f), i1 = 0.5f / (s1 + 1e-16f);
    float4 b4 = __ldg(((const float4*)bias) + lane);
    float4 o4;
    o4.x = sig_(acc0.x * i0 + acc1.x * i1 + b4.x);
    o4.y = sig_(acc0.y * i0 + acc1.y * i1 + b4.y);
    o4.z = sig_(acc0.z * i0 + acc1.z * i1 + b4.z);
    o4.w = sig_(acc0.w * i0 + acc1.w * i1 + b4.w);
    ((float4*)(out + (size_t)n * 128))[lane] = o4;
}

// ---------------- gate: BN + relu elementwise ----------------
__global__ void k_bnrelu(const float* __restrict__ gb1,
                         const float* __restrict__ bng, const float* __restrict__ bnb,
                         const float* __restrict__ bnm, const float* __restrict__ bnv) {
    long long t = (long long)blockIdx.x * blockDim.x + threadIdx.x;
    if (t >= (long long)NN * 128) return;
    int j = (int)(t & 127);
    float v = (d_gh[t] + gb1[j] - bnm[j]) * rsqrtf(bnv[j] + 1e-5f) * bng[j] + bnb[j];
    d_gh[t] = v > 0.f ? v : 0.f;
}

// ---------------- gate logit ----------------
__global__ void k_lg(const float* __restrict__ gw2, const float* __restrict__ gb2) {
    int n = blockIdx.x * 8 + (threadIdx.x >> 5);
    int lane = threadIdx.x & 31;
    if (n >= NN) return;
    float4 g = __ldg((const float4*)(d_gh + (size_t)n * 128) + lane);
    float4 w = __ldg((const float4*)gw2 + lane);
    float p = warpSum(dot4(g, w));
    if (lane == 0) d_lg[n] = p + __ldg(gb2);
}

// ---------------- gate softmax + pooling ----------------
__global__ void k_zg() {
    int t = blockIdx.x * blockDim.x + threadIdx.x;
    if (t < GG * 128) d_pooled[t] = 0.f;
    if (t < GG) d_gs[t] = 0.f;
}
__global__ void k_gsum(const int* __restrict__ batch) {
    int n = blockIdx.x * blockDim.x + threadIdx.x;
    if (n >= NN) return;
    float e = __expf(d_lg[n]);
    d_eg[n] = e;
    atomicAdd(&d_gs[gi(batch, n, d_i64)], e);
}
__global__ void k_gpool(const int* __restrict__ batch) {
    long long t = (long long)blockIdx.x * blockDim.x + threadIdx.x;
    if (t >= (long long)NN * 32) return;
    int n = (int)(t >> 5), q = (int)(t & 31);
    int b = gi(batch, n, d_i64);
    float gate = d_eg[n] / (d_gs[b] + 1e-16f);
    float4 v = __ldg((const float4*)(d_out2 + (size_t)n * 128) + q);
    float* pp = d_pooled + b * 128 + q * 4;
    atomicAdd(pp + 0, gate * v.x);
    atomicAdd(pp + 1, gate * v.y);
    atomicAdd(pp + 2, gate * v.z);
    atomicAdd(pp + 3, gate * v.w);
}
__global__ void k_fin(const float* __restrict__ glw, const float* __restrict__ glb,
                      float* __restrict__ out) {
    int g = (blockIdx.x * blockDim.x + threadIdx.x) >> 5;
    int lane = threadIdx.x & 31;
    if (g >= GG) return;
    float4 p = ((const float4*)(d_pooled + g * 128))[lane];
    float4 w = __ldg((const float4*)glw + lane);
    float acc = warpSum(dot4(p, w));
    if (lane == 0) out[g] = sig_(acc + __ldg(glb));
}

// ---------------- launch ----------------
extern "C" void kernel_launch(void* const* d_in, const int* in_sizes, int n_in,
                              void* d_out, int out_size) {
    const int* x     = (const int*)d_in[0];
    const int* ei    = (const int*)d_in[1];
    const int* batch = (const int*)d_in[3];
    const float* emb0 = (const float*)d_in[4];
    const float* emb1 = (const float*)d_in[5];
    const float* emb2 = (const float*)d_in[6];
    const float* emb3 = (const float*)d_in[7];
    const float* emb4 = (const float*)d_in[8];
    const float* emb5 = (const float*)d_in[9];
    const float* W1  = (const float*)d_in[10];
    const float* as1 = (const float*)d_in[11];
    const float* ad1 = (const float*)d_in[12];
    const float* b1  = (const float*)d_in[13];
    const float* W2  = (const float*)d_in[14];
    const float* as2 = (const float*)d_in[15];
    const float* ad2 = (const float*)d_in[16];
    const float* b2  = (const float*)d_in[17];
    const float* gw1 = (const float*)d_in[18];
    const float* gb1 = (const float*)d_in[19];
    const float* bng = (const float*)d_in[20];
    const float* bnb = (const float*)d_in[21];
    const float* bnm = (const float*)d_in[22];
    const float* bnv = (const float*)d_in[23];
    const float* gw2 = (const float*)d_in[24];
    const float* gb2 = (const float*)d_in[25];
    const float* glw = (const float*)d_in[26];
    const float* glb = (const float*)d_in[27];
    float* out = (float*)d_out;

    float* p_h;  cudaGetSymbolAddress((void**)&p_h, d_h);
    float* p_x;  cudaGetSymbolAddress((void**)&p_x, d_x384);
    float* p_o1; cudaGetSymbolAddress((void**)&p_o1, d_out1);
    float* p_o2; cudaGetSymbolAddress((void**)&p_o2, d_out2);
    float* p_gh; cudaGetSymbolAddress((void**)&p_gh, d_gh);

    const int smem256 = (128 * 256 + 64 * 128) * 4;
    const int smem128 = (128 * 128 + 64 * 128) * 4;
    cudaFuncSetAttribute((const void*)k_sgemm<256, 384>, cudaFuncAttributeMaxDynamicSharedMemorySize, smem256);
    cudaFuncSetAttribute((const void*)k_sgemm<256, 128>, cudaFuncAttributeMaxDynamicSharedMemorySize, smem256);
    cudaFuncSetAttribute((const void*)k_sgemm<128, 128>, cudaFuncAttributeMaxDynamicSharedMemorySize, smem128);

    const long long NF = (long long)NN * 128;
    const int gNF = (int)((NF + 255) / 256);
    const int gNODE = NN / 8;
    const int gGEMM = (NN + 63) / 64;

    k_detect<<<1, 32>>>(ei);

    // CSR build
    k_init<<<(NN + 255) / 256, 256>>>();
    k_hist<<<(EE + 255) / 256, 256>>>(ei);
    k_scan1<<<NB, 1024>>>();
    k_scan2<<<1, 32>>>();
    k_scan3<<<NB, 1024>>>();
    k_scatter<<<(ET + 255) / 256, 256>>>(ei);

    // layer 1
    k_x384<<<(int)(((long long)NN * 96 + 255) / 256), 256>>>(x, emb0, emb1, emb2, emb3, emb4, emb5);
    k_sgemm<256, 384><<<gGEMM, 512, smem256>>>(p_x, W1, p_h, NN);
    k_al<<<gNODE, 256>>>(as1, ad1);
    k_gat<<<gNODE, 256>>>(b1, p_o1);

    // layer 2
    k_sgemm<256, 128><<<gGEMM, 512, smem256>>>(p_o1, W2, p_h, NN);
    k_al<<<gNODE, 256>>>(as2, ad2);
    k_gat<<<gNODE, 256>>>(b2, p_o2);

    // gate + pooling
    k_sgemm<128, 128><<<gGEMM, 512, smem128>>>(p_o2, gw1, p_gh, NN);
    k_bnrelu<<<gNF, 256>>>(gb1, bng, bnb, bnm, bnv);
    k_lg<<<gNODE, 256>>>(gw2, gb2);
    k_zg<<<(GG * 128 + 255) / 256, 256>>>();
    k_gsum<<<(NN + 255) / 256, 256>>>(batch);
    k_gpool<<<(int)(((long long)NN * 32 + 255) / 256), 256>>>(batch);
    k_fin<<<(GG * 32 + 255) / 256, 256>>>(glw, glb, out);

    (void)in_sizes; (void)n_in; (void)out_size;
}

// round 6
// speedup vs baseline: 5.1972x; 1.7574x over previous
#include <cuda_runtime.h>
#include <math.h>

#define NN 100000
#define EE 800000
#define ET (EE + NN)
#define GG 128
#define NB 98   /* ceil(NN/1024) */
#define FULL 0xffffffffu

typedef unsigned long long ull;

// ---------------- scratch (static device memory) ----------------
__device__ float d_h[(size_t)NN * 256];
__device__ float d_out1[(size_t)NN * 128];
__device__ float d_out2[(size_t)NN * 128];
__device__ float d_als[NN * 2], d_ald[NN * 2];
__device__ float d_ew[(size_t)ET * 2];
__device__ float d_gh[(size_t)NN * 128];
__device__ float d_lg[NN], d_eg[NN];
__device__ float d_gs[GG];
__device__ float d_pooled[GG * 128];
__device__ float d_T1[50 * 256];
__device__ int d_deg[NN], d_incl[NN], d_ptr[NN + 1], d_pos[NN];
__device__ int d_srcs[ET], d_dstv[ET];
__device__ int d_bsum[128], d_boff[128];
__device__ int d_i64;

__constant__ int c_voff[6] = {0, 33, 38, 41, 45, 47};

// ---------------- helpers ----------------
__device__ __forceinline__ float sig_(float x) { return 1.f / (1.f + __expf(-x)); }
__device__ __forceinline__ float lrelu_(float x) { return x > 0.f ? x : 0.2f * x; }
__device__ __forceinline__ float warpSum(float v) {
#pragma unroll
    for (int o = 16; o; o >>= 1) v += __shfl_xor_sync(FULL, v, o);
    return v;
}
__device__ __forceinline__ float dot4(float4 a, float4 b) {
    return a.x * b.x + a.y * b.y + a.z * b.z + a.w * b.w;
}
__device__ __forceinline__ int gi(const int* __restrict__ p, int i, int m64) {
    return p[m64 ? (i << 1) : i];
}
__device__ __forceinline__ ull pack2(float x, float y) {
    ull r;
    asm("mov.b64 %0, {%1, %2};" : "=l"(r) : "f"(x), "f"(y));
    return r;
}
__device__ __forceinline__ void ffma2(ull& d, ull a, ull b) {
    asm("fma.rn.f32x2 %0, %1, %2, %0;" : "+l"(d) : "l"(a), "l"(b));
}

__global__ void k_detect(const int* __restrict__ ei) {
    if (threadIdx.x == 0)
        d_i64 = ((ei[1] | ei[3] | ei[5] | ei[7] | ei[9]) == 0) ? 1 : 0;
}

// ---------------- CSR build ----------------
__global__ void k_init() {
    int i = blockIdx.x * blockDim.x + threadIdx.x;
    if (i < NN) d_deg[i] = 1;
}
__global__ void k_hist(const int* __restrict__ ei) {
    int t = blockIdx.x * blockDim.x + threadIdx.x;
    if (t < EE) atomicAdd(&d_deg[gi(ei, EE + t, d_i64)], 1);
}
__global__ void k_scan1() {
    __shared__ int ws[32];
    int i = blockIdx.x * 1024 + threadIdx.x;
    int lane = threadIdx.x & 31, w = threadIdx.x >> 5;
    int x = (i < NN) ? d_deg[i] : 0;
#pragma unroll
    for (int o = 1; o < 32; o <<= 1) { int y = __shfl_up_sync(FULL, x, o); if (lane >= o) x += y; }
    if (lane == 31) ws[w] = x;
    __syncthreads();
    if (w == 0) {
        int t = ws[lane];
#pragma unroll
        for (int o = 1; o < 32; o <<= 1) { int y = __shfl_up_sync(FULL, t, o); if (lane >= o) t += y; }
        ws[lane] = t;
    }
    __syncthreads();
    x += (w > 0) ? ws[w - 1] : 0;
    if (i < NN) d_incl[i] = x;
    if (threadIdx.x == 1023) d_bsum[blockIdx.x] = x;
}
__global__ void k_scan2() {
    if (threadIdx.x == 0) {
        int r = 0;
        for (int b = 0; b < NB; b++) { d_boff[b] = r; r += d_bsum[b]; }
    }
}
__global__ void k_scan3() {
    int i = blockIdx.x * 1024 + threadIdx.x;
    if (i < NN) {
        int e = d_incl[i] - d_deg[i] + d_boff[blockIdx.x];
        d_ptr[i] = e;
        d_pos[i] = e;
    }
    if (i == 0) d_ptr[NN] = ET;
}
__global__ void k_scatter(const int* __restrict__ ei) {
    int t = blockIdx.x * blockDim.x + threadIdx.x;
    if (t >= ET) return;
    int m64 = d_i64;
    int s, d;
    if (t < EE) { s = gi(ei, t, m64); d = gi(ei, EE + t, m64); }
    else { s = d = t - EE; }
    int idx = atomicAdd(&d_pos[d], 1);
    d_srcs[idx] = s;
    d_dstv[idx] = d;
}

// ---------------- T1 = emb_i @ W1_i  (50 x 256) ----------------
__global__ void k_T1(const float* __restrict__ e0, const float* __restrict__ e1,
                     const float* __restrict__ e2, const float* __restrict__ e3,
                     const float* __restrict__ e4, const float* __restrict__ e5,
                     const float* __restrict__ W1) {
    int row = blockIdx.x;      // 0..49
    int j = threadIdx.x;       // 0..255
    int i, v;
    if (row < 33)      { i = 0; v = row; }
    else if (row < 38) { i = 1; v = row - 33; }
    else if (row < 41) { i = 2; v = row - 38; }
    else if (row < 45) { i = 3; v = row - 41; }
    else if (row < 47) { i = 4; v = row - 45; }
    else               { i = 5; v = row - 47; }
    const float* emb = (i == 0) ? e0 : (i == 1) ? e1 : (i == 2) ? e2 : (i == 3) ? e3 : (i == 4) ? e4 : e5;
    float acc = 0.f;
#pragma unroll 8
    for (int c = 0; c < 64; c++) acc = fmaf(emb[v * 64 + c], W1[(size_t)(i * 64 + c) * 256 + j], acc);
    d_T1[row * 256 + j] = acc;
}

// ---------------- h1 = sum_i T1[voff_i + x[n,i]] : warp per node ----------------
__global__ void k_embed(const int* __restrict__ x) {
    int n = blockIdx.x * 8 + (threadIdx.x >> 5);
    int lane = threadIdx.x & 31;
    if (n >= NN) return;
    int m64 = d_i64;
    int xv = 0;
    if (lane < 6) xv = gi(x, n * 6 + lane, m64);
    int rows[6];
#pragma unroll
    for (int i = 0; i < 6; i++) rows[i] = c_voff[i] + __shfl_sync(FULL, xv, i);
    float4 a0 = make_float4(0.f, 0.f, 0.f, 0.f), a1 = make_float4(0.f, 0.f, 0.f, 0.f);
#pragma unroll
    for (int i = 0; i < 6; i++) {
        const float4* T = (const float4*)(d_T1 + rows[i] * 256);
        float4 t0 = T[lane], t1 = T[lane + 32];
        a0.x += t0.x; a0.y += t0.y; a0.z += t0.z; a0.w += t0.w;
        a1.x += t1.x; a1.y += t1.y; a1.z += t1.z; a1.w += t1.w;
    }
    float4* hp = (float4*)(d_h + (size_t)n * 256);
    hp[lane] = a0; hp[lane + 32] = a1;
}

// ---------------- tiled SGEMM: C[M,NC] = A[M,KT] @ B[KT,NC], f32x2 FMA ----------------
template <int NC, int KT>
__global__ void k_sgemm(const float* __restrict__ A, const float* __restrict__ B,
                        float* __restrict__ C, int M) {
    constexpr int BM = 64, BK = 128, NR = NC / 32;
    extern __shared__ float sm[];
    float* Bs = sm;            // [BK][NC]
    float* As = sm + BK * NC;  // [BM][BK]
    int tid = threadIdx.x;
    int row0 = blockIdx.x * BM;
    int tn = tid & 31, tm = tid >> 5;

    ull acc2[4][NR / 2];
#pragma unroll
    for (int r = 0; r < 4; r++)
#pragma unroll
        for (int q = 0; q < NR / 2; q++) acc2[r][q] = 0ull;

    for (int k0 = 0; k0 < KT; k0 += BK) {
        {
            const float4* Bg = (const float4*)(B + (size_t)k0 * NC);
            float4* Bs4 = (float4*)Bs;
#pragma unroll
            for (int u = 0; u < (BK * NC / 4) / 512; u++)
                Bs4[tid + 512 * u] = __ldg(Bg + tid + 512 * u);
        }
        {
            float4* As4 = (float4*)As;
#pragma unroll
            for (int u = 0; u < (BM * BK / 4) / 512; u++) {
                int f = tid + 512 * u;
                int r = f >> 5, c4 = f & 31;
                int gr = row0 + r;
                float4 v = make_float4(0.f, 0.f, 0.f, 0.f);
                if (gr < M) v = __ldg((const float4*)(A + (size_t)gr * KT) + (k0 >> 2) + c4);
                As4[f] = v;
            }
        }
        __syncthreads();
        const float* Ab = As + (tm * 4) * BK;
#pragma unroll 4
        for (int k = 0; k < BK; k++) {
            ull a2[4];
#pragma unroll
            for (int r = 0; r < 4; r++) { float av = Ab[r * BK + k]; a2[r] = pack2(av, av); }
            ull b2[NR / 2];
            const float4* bp = (const float4*)(Bs + k * NC + tn * NR);
#pragma unroll
            for (int q = 0; q < NR / 4; q++) {
                float4 tv = bp[q];
                b2[2 * q]     = pack2(tv.x, tv.y);
                b2[2 * q + 1] = pack2(tv.z, tv.w);
            }
#pragma unroll
            for (int r = 0; r < 4; r++)
#pragma unroll
                for (int q = 0; q < NR / 2; q++) ffma2(acc2[r][q], a2[r], b2[q]);
        }
        __syncthreads();
    }
#pragma unroll
    for (int r = 0; r < 4; r++) {
        int gr = row0 + tm * 4 + r;
        if (gr < M) {
            ull* cp = (ull*)(C + (size_t)gr * NC + tn * NR);
#pragma unroll
            for (int q = 0; q < NR / 2; q++) cp[q] = acc2[r][q];
        }
    }
}

// ---------------- attention logits: warp per node, float4 ----------------
__global__ void k_al(const float* __restrict__ as_, const float* __restrict__ ad_) {
    int n = blockIdx.x * 8 + (threadIdx.x >> 5);
    int lane = threadIdx.x & 31;
    if (n >= NN) return;
    const float4* hp = (const float4*)(d_h + (size_t)n * 256);
    float4 h0 = __ldg(hp + lane), h1 = __ldg(hp + lane + 32);
    float4 s0 = __ldg((const float4*)as_ + lane), s1 = __ldg((const float4*)as_ + lane + 32);
    float4 t0 = __ldg((const float4*)ad_ + lane), t1 = __ldg((const float4*)ad_ + lane + 32);
    float ps0 = warpSum(dot4(h0, s0));
    float ps1 = warpSum(dot4(h1, s1));
    float pd0 = warpSum(dot4(h0, t0));
    float pd1 = warpSum(dot4(h1, t1));
    if (lane == 0) {
        d_als[n * 2] = ps0; d_als[n * 2 + 1] = ps1;
        d_ald[n * 2] = pd0; d_ald[n * 2 + 1] = pd1;
    }
}

// ---------------- per-edge weights: w = exp(leaky(als[s]+ald[d])) ----------------
__global__ void k_ew() {
    int t = blockIdx.x * blockDim.x + threadIdx.x;
    if (t >= ET) return;
    int s = d_srcs[t], d = d_dstv[t];
    float2 asv = ((const float2*)d_als)[s];
    float2 adv = ((const float2*)d_ald)[d];
    float w0 = __expf(lrelu_(asv.x + adv.x));
    float w1 = __expf(lrelu_(asv.y + adv.y));
    ((float2*)d_ew)[t] = make_float2(w0, w1);
}

// ---------------- fused GAT: shuffle-free gather, warp per dst ----------------
__global__ void k_gat(const float* __restrict__ bias, float* __restrict__ out) {
    int n = blockIdx.x * 8 + (threadIdx.x >> 5);
    int lane = threadIdx.x & 31;
    if (n >= NN) return;
    int p0 = d_ptr[n], p1 = d_ptr[n + 1];

    float4 acc0 = make_float4(0.f, 0.f, 0.f, 0.f);
    float4 acc1 = make_float4(0.f, 0.f, 0.f, 0.f);
    float s0 = 0.f, s1 = 0.f;

#pragma unroll 2
    for (int j = p0; j < p1; j++) {
        int s = __ldg(&d_srcs[j]);                     // uniform (warp-broadcast)
        float2 w = __ldg(((const float2*)d_ew) + j);   // uniform
        s0 += w.x; s1 += w.y;
        const float4* hp = (const float4*)(d_h + (size_t)s * 256);
        float4 v0 = __ldg(hp + lane);
        float4 v1 = __ldg(hp + lane + 32);
        acc0.x = fmaf(w.x, v0.x, acc0.x); acc1.x = fmaf(w.y, v1.x, acc1.x);
        acc0.y = fmaf(w.x, v0.y, acc0.y); acc1.y = fmaf(w.y, v1.y, acc1.y);
        acc0.z = fmaf(w.x, v0.z, acc0.z); acc1.z = fmaf(w.y, v1.z, acc1.z);
        acc0.w = fmaf(w.x, v0.w, acc0.w); acc1.w = fmaf(w.y, v1.w, acc1.w);
    }
    float i0 = 0.5f / (s0 + 1e-16f), i1 = 0.5f / (s1 + 1e-16f);
    float4 b4 = __ldg(((const float4*)bias) + lane);
    float4 o4;
    o4.x = sig_(acc0.x * i0 + acc1.x * i1 + b4.x);
    o4.y = sig_(acc0.y * i0 + acc1.y * i1 + b4.y);
    o4.z = sig_(acc0.z * i0 + acc1.z * i1 + b4.z);
    o4.w = sig_(acc0.w * i0 + acc1.w * i1 + b4.w);
    ((float4*)(out + (size_t)n * 128))[lane] = o4;
}

// ---------------- gate: BN + relu elementwise ----------------
__global__ void k_bnrelu(const float* __restrict__ gb1,
                         const float* __restrict__ bng, const float* __restrict__ bnb,
                         const float* __restrict__ bnm, const float* __restrict__ bnv) {
    long long t = (long long)blockIdx.x * blockDim.x + threadIdx.x;
    if (t >= (long long)NN * 128) return;
    int j = (int)(t & 127);
    float v = (d_gh[t] + gb1[j] - bnm[j]) * rsqrtf(bnv[j] + 1e-5f) * bng[j] + bnb[j];
    d_gh[t] = v > 0.f ? v : 0.f;
}

// ---------------- gate logit ----------------
__global__ void k_lg(const float* __restrict__ gw2, const float* __restrict__ gb2) {
    int n = blockIdx.x * 8 + (threadIdx.x >> 5);
    int lane = threadIdx.x & 31;
    if (n >= NN) return;
    float4 g = __ldg((const float4*)(d_gh + (size_t)n * 128) + lane);
    float4 w = __ldg((const float4*)gw2 + lane);
    float p = warpSum(dot4(g, w));
    if (lane == 0) d_lg[n] = p + __ldg(gb2);
}

// ---------------- gate softmax + pooling ----------------
__global__ void k_zg() {
    int t = blockIdx.x * blockDim.x + threadIdx.x;
    if (t < GG * 128) d_pooled[t] = 0.f;
    if (t < GG) d_gs[t] = 0.f;
}
__global__ void k_gsum(const int* __restrict__ batch) {
    int n = blockIdx.x * blockDim.x + threadIdx.x;
    if (n >= NN) return;
    float e = __expf(d_lg[n]);
    d_eg[n] = e;
    atomicAdd(&d_gs[gi(batch, n, d_i64)], e);
}
__global__ void k_gpool(const int* __restrict__ batch) {
    long long t = (long long)blockIdx.x * blockDim.x + threadIdx.x;
    if (t >= (long long)NN * 32) return;
    int n = (int)(t >> 5), q = (int)(t & 31);
    int b = gi(batch, n, d_i64);
    float gate = d_eg[n] / (d_gs[b] + 1e-16f);
    float4 v = __ldg((const float4*)(d_out2 + (size_t)n * 128) + q);
    float* pp = d_pooled + b * 128 + q * 4;
    atomicAdd(pp + 0, gate * v.x);
    atomicAdd(pp + 1, gate * v.y);
    atomicAdd(pp + 2, gate * v.z);
    atomicAdd(pp + 3, gate * v.w);
}
__global__ void k_fin(const float* __restrict__ glw, const float* __restrict__ glb,
                      float* __restrict__ out) {
    int g = (blockIdx.x * blockDim.x + threadIdx.x) >> 5;
    int lane = threadIdx.x & 31;
    if (g >= GG) return;
    float4 p = ((const float4*)(d_pooled + g * 128))[lane];
    float4 w = __ldg((const float4*)glw + lane);
    float acc = warpSum(dot4(p, w));
    if (lane == 0) out[g] = sig_(acc + __ldg(glb));
}

// ---------------- launch ----------------
extern "C" void kernel_launch(void* const* d_in, const int* in_sizes, int n_in,
                              void* d_out, int out_size) {
    const int* x     = (const int*)d_in[0];
    const int* ei    = (const int*)d_in[1];
    const int* batch = (const int*)d_in[3];
    const float* emb0 = (const float*)d_in[4];
    const float* emb1 = (const float*)d_in[5];
    const float* emb2 = (const float*)d_in[6];
    const float* emb3 = (const float*)d_in[7];
    const float* emb4 = (const float*)d_in[8];
    const float* emb5 = (const float*)d_in[9];
    const float* W1  = (const float*)d_in[10];
    const float* as1 = (const float*)d_in[11];
    const float* ad1 = (const float*)d_in[12];
    const float* b1  = (const float*)d_in[13];
    const float* W2  = (const float*)d_in[14];
    const float* as2 = (const float*)d_in[15];
    const float* ad2 = (const float*)d_in[16];
    const float* b2  = (const float*)d_in[17];
    const float* gw1 = (const float*)d_in[18];
    const float* gb1 = (const float*)d_in[19];
    const float* bng = (const float*)d_in[20];
    const float* bnb = (const float*)d_in[21];
    const float* bnm = (const float*)d_in[22];
    const float* bnv = (const float*)d_in[23];
    const float* gw2 = (const float*)d_in[24];
    const float* gb2 = (const float*)d_in[25];
    const float* glw = (const float*)d_in[26];
    const float* glb = (const float*)d_in[27];
    float* out = (float*)d_out;

    float* p_h;  cudaGetSymbolAddress((void**)&p_h, d_h);
    float* p_o1; cudaGetSymbolAddress((void**)&p_o1, d_out1);
    float* p_o2; cudaGetSymbolAddress((void**)&p_o2, d_out2);
    float* p_gh; cudaGetSymbolAddress((void**)&p_gh, d_gh);

    const int smem256 = (128 * 256 + 64 * 128) * 4;
    const int smem128 = (128 * 128 + 64 * 128) * 4;
    cudaFuncSetAttribute((const void*)k_sgemm<256, 128>, cudaFuncAttributeMaxDynamicSharedMemorySize, smem256);
    cudaFuncSetAttribute((const void*)k_sgemm<128, 128>, cudaFuncAttributeMaxDynamicSharedMemorySize, smem128);

    const long long NF = (long long)NN * 128;
    const int gNF = (int)((NF + 255) / 256);
    const int gNODE = NN / 8;
    const int gGEMM = (NN + 63) / 64;
    const int gEDGE = (ET + 255) / 256;

    k_detect<<<1, 32>>>(ei);

    // CSR build
    k_init<<<(NN + 255) / 256, 256>>>();
    k_hist<<<(EE + 255) / 256, 256>>>(ei);
    k_scan1<<<NB, 1024>>>();
    k_scan2<<<1, 32>>>();
    k_scan3<<<NB, 1024>>>();
    k_scatter<<<gEDGE, 256>>>(ei);

    // layer 1 (T1-factorized input GEMM)
    k_T1<<<50, 256>>>(emb0, emb1, emb2, emb3, emb4, emb5, W1);
    k_embed<<<gNODE, 256>>>(x);
    k_al<<<gNODE, 256>>>(as1, ad1);
    k_ew<<<gEDGE, 256>>>();
    k_gat<<<gNODE, 256>>>(b1, p_o1);

    // layer 2
    k_sgemm<256, 128><<<gGEMM, 512, smem256>>>(p_o1, W2, p_h, NN);
    k_al<<<gNODE, 256>>>(as2, ad2);
    k_ew<<<gEDGE, 256>>>();
    k_gat<<<gNODE, 256>>>(b2, p_o2);

    // gate + pooling
    k_sgemm<128, 128><<<gGEMM, 512, smem128>>>(p_o2, gw1, p_gh, NN);
    k_bnrelu<<<gNF, 256>>>(gb1, bng, bnb, bnm, bnv);
    k_lg<<<gNODE, 256>>>(gw2, gb2);
    k_zg<<<(GG * 128 + 255) / 256, 256>>>();
    k_gsum<<<(NN + 255) / 256, 256>>>(batch);
    k_gpool<<<(int)(((long long)NN * 32 + 255) / 256), 256>>>(batch);
    k_fin<<<(GG * 32 + 255) / 256, 256>>>(glw, glb, out);

    (void)in_sizes; (void)n_in; (void)out_size;
}